// round 14
// baseline (speedup 1.0000x reference)
#include <cstdint>
#include <cuda_runtime.h>
#include <cuda_bf16.h>
#include <mma.h>

using namespace nvcuda;
typedef __nv_bfloat16 bf;

#define Bn 2
#define Dm 256
#define Cc 64
#define Tt 1024
#define Hh 8
#define Ff 32
#define CT 65536
#define E3 768
#define EPS 1e-5f
#define SCALE 0.1767766952966369f

// ---------------- scratch ----------------
__device__ __align__(128) bf g_xbf[(size_t)Bn * Dm * CT];      // 67 MB
__device__ __align__(128) bf g_qt[(size_t)Bn * Dm * CT];       // q~ only
__device__ __align__(128) bf g_weff[(size_t)Bn * E3 * Dm];
__device__ float g_mu[Bn * Dm];
__device__ float g_rstd[Bn * Dm];
__device__ float g_bias[Bn * E3];
__device__ __align__(128) bf g_wout[Dm * Dm];
__device__ __align__(128) float g_ctxp[(size_t)Bn * Cc * 8 * Hh * Ff * Ff];
__device__ __align__(128) float g_Sp[(size_t)Bn * Cc * 8 * 256];
__device__ __align__(128) bf g_mcat[(size_t)Bn * Cc * Dm * Dm];

// ---------------- cp.async ----------------
__device__ __forceinline__ void cp16(void* smem, const void* gmem) {
    unsigned s = (unsigned)__cvta_generic_to_shared(smem);
    asm volatile("cp.async.cg.shared.global [%0], [%1], 16;\n" :: "r"(s), "l"(gmem));
}
#define CP_COMMIT() asm volatile("cp.async.commit_group;\n")
#define CP_WAIT1()  asm volatile("cp.async.wait_group 1;\n")
#define CP_WAIT0()  asm volatile("cp.async.wait_group 0;\n")

// ---------------- K1: stats + convert x to bf16 ----------------
__global__ __launch_bounds__(256) void stats_cvt(const float* __restrict__ x) {
    size_t base = (size_t)blockIdx.x * CT;
    const float4* p = (const float4*)(x + base);
    bf* ob = g_xbf + base;
    float s = 0.f, ss = 0.f;
    for (int i = threadIdx.x; i < CT / 4; i += 256) {
        float4 v = p[i];
        s += v.x + v.y + v.z + v.w;
        ss += v.x * v.x + v.y * v.y + v.z * v.z + v.w * v.w;
        union { uint2 u; __nv_bfloat162 h[2]; } pk;
        pk.h[0] = __floats2bfloat162_rn(v.x, v.y);
        pk.h[1] = __floats2bfloat162_rn(v.z, v.w);
        *(uint2*)(ob + (size_t)i * 4) = pk.u;
    }
    __shared__ float rs[8], rss[8];
    for (int off = 16; off; off >>= 1) {
        s  += __shfl_down_sync(~0u, s, off);
        ss += __shfl_down_sync(~0u, ss, off);
    }
    int wid = threadIdx.x >> 5, lane = threadIdx.x & 31;
    if (lane == 0) { rs[wid] = s; rss[wid] = ss; }
    __syncthreads();
    if (threadIdx.x == 0) {
        float S = 0.f, SS = 0.f;
        for (int i = 0; i < 8; i++) { S += rs[i]; SS += rss[i]; }
        float mu = S / (float)CT;
        float var = SS / (float)CT - mu * mu;
        g_mu[blockIdx.x] = mu;
        g_rstd[blockIdx.x] = rsqrtf(var + EPS);
    }
}

// ---------------- K2: fold instance norm into weights ----------------
__global__ __launch_bounds__(256) void prep_weights(const float* __restrict__ in_w,
                                                    const float* __restrict__ in_b) {
    int be = blockIdx.x;
    int b = be / E3, e = be % E3;
    int d = threadIdx.x;
    float w = in_w[e * Dm + d];
    float r = g_rstd[b * Dm + d];
    float m = g_mu[b * Dm + d];
    float we = w * r;
    g_weff[(size_t)be * Dm + d] = __float2bfloat16(we);
    __shared__ float red[256];
    red[d] = we * m;
    __syncthreads();
    for (int s = 128; s > 0; s >>= 1) {
        if (d < s) red[d] += red[d + s];
        __syncthreads();
    }
    if (d == 0) g_bias[be] = in_b[e] - red[0];
}

__global__ __launch_bounds__(256) void conv_outw(const float* __restrict__ out_w) {
    int i = blockIdx.x * 256 + threadIdx.x;
    g_wout[i] = __float2bfloat16(out_w[i]);
}

// ---------------- K3: unified qkv kernel, 128 thr, 64x64 warp tiles, 3-stage ----------------
// grid (6, 512, 2). et 0-1: q rows et*128 (softmax epi -> g_qt).
// et 2-5: kv head pair hp=et-2 (64 k rows + 64 v rows; exp/ctx-partial epi).
// smem: A[3][128][72] @0 (55296), B[3][64][136] @55296 (52224),
//   q overlays: stage f32[128][132] @0 (67584)
//   kv overlays: kbuf[64][136] @0, vbuf @17408; scratch @55296, hstage @60416
//   biasT @107520 (512), S_s @108032 (512). total 108544 (2 CTAs/SM).
#define U_SB    55296
#define U_VB    17408
#define U_SCR   55296
#define U_HST   60416
#define U_BIAS  107520
#define U_SS    108032
#define U_SMEM  108544

__global__ __launch_bounds__(128) void qkv_unified() {
    extern __shared__ __align__(16) char sm[];
    bf (*A_s)[128][72] = (bf(*)[128][72])sm;
    bf (*B_s)[64][136] = (bf(*)[64][136])(sm + U_SB);
    float (*stage)[132] = (float(*)[132])sm;
    bf (*kbuf)[136] = (bf(*)[136])sm;
    bf (*vbuf)[136] = (bf(*)[136])(sm + U_VB);
    float* biasT = (float*)(sm + U_BIAS);
    float* S_s   = (float*)(sm + U_SS);

    const int et = blockIdx.x;   // 0-1 q, 2-5 kv head pair
    const int tt = blockIdx.y;
    const int b  = blockIdx.z;
    const bool is_q = (et < 2);
    const int hp = et - 2;

    const int tid = threadIdx.x;
    const int w = tid >> 5, lane = tid & 31;
    const int wm = w >> 1, wn = w & 1;

    auto rowmap = [&](int r) {
        if (is_q) return et * 128 + r;
        return r < 64 ? (256 + hp * 64 + r) : (512 + hp * 64 + r - 64);
    };
    biasT[tid] = g_bias[b * E3 + rowmap(tid)];

    const bf* Wb = g_weff + (size_t)b * E3 * Dm;
    const bf* Bptr = g_xbf + (size_t)b * Dm * CT + (size_t)tt * 128;

    wmma::fragment<wmma::accumulator, 16, 16, 16, float> acc[4][4];
    #pragma unroll
    for (int i = 0; i < 4; i++)
        #pragma unroll
        for (int j = 0; j < 4; j++) wmma::fill_fragment(acc[i][j], 0.0f);

    auto loadA = [&](int s, int k0) {
        #pragma unroll
        for (int it = 0; it < 8; it++) {
            int idx = tid + it * 128;
            int r = idx >> 3, c8 = (idx & 7) * 8;
            cp16(&A_s[s][r][c8], Wb + (size_t)rowmap(r) * Dm + k0 + c8);
        }
    };
    auto loadB = [&](int s, int k0) {
        #pragma unroll
        for (int it = 0; it < 8; it++) {
            int idx = tid + it * 128;
            int r = idx >> 4, c8 = (idx & 15) * 8;
            cp16(&B_s[s][r][c8], Bptr + (size_t)(k0 + r) * CT + c8);
        }
    };
    auto mma_chunk = [&](int st) {
        #pragma unroll
        for (int kk = 0; kk < 64; kk += 16) {
            wmma::fragment<wmma::matrix_a, 16, 16, 16, bf, wmma::row_major> af[4];
            wmma::fragment<wmma::matrix_b, 16, 16, 16, bf, wmma::row_major> bfr[4];
            #pragma unroll
            for (int i = 0; i < 4; i++)
                wmma::load_matrix_sync(af[i], &A_s[st][wm * 64 + i * 16][kk], 72);
            #pragma unroll
            for (int j = 0; j < 4; j++)
                wmma::load_matrix_sync(bfr[j], &B_s[st][kk][wn * 64 + j * 16], 136);
            #pragma unroll
            for (int i = 0; i < 4; i++)
                #pragma unroll
                for (int j = 0; j < 4; j++)
                    wmma::mma_sync(acc[i][j], af[i], bfr[j], acc[i][j]);
        }
    };

    loadA(0, 0);   loadB(0, 0);   CP_COMMIT();
    loadA(1, 64);  loadB(1, 64);  CP_COMMIT();
    CP_WAIT1(); __syncthreads();
    mma_chunk(0);
    loadA(2, 128); loadB(2, 128); CP_COMMIT();
    CP_WAIT1(); __syncthreads();
    mma_chunk(1);
    loadA(0, 192); loadB(0, 192); CP_COMMIT();
    CP_WAIT1(); __syncthreads();
    mma_chunk(2);
    CP_WAIT0(); __syncthreads();
    mma_chunk(0);
    __syncthreads();   // buffers dead; overlays live

    if (is_q) {
        #pragma unroll
        for (int i = 0; i < 4; i++)
            #pragma unroll
            for (int j = 0; j < 4; j++)
                wmma::store_matrix_sync(&stage[wm * 64 + i * 16][wn * 64 + j * 16],
                                        acc[i][j], 132, wmma::mem_row_major);
        __syncthreads();
        {   // column softmax per 32-row head block (4 blocks); bias folded
            int col = tid;
            #pragma unroll
            for (int hb = 0; hb < 4; hb++) {
                float vbuf2[32];
                float m = -1e30f;
                #pragma unroll
                for (int rr = 0; rr < 32; rr++) {
                    float vv = stage[hb * 32 + rr][col] + biasT[hb * 32 + rr];
                    vbuf2[rr] = vv; m = fmaxf(m, vv);
                }
                float s = 0.f;
                #pragma unroll
                for (int rr = 0; rr < 32; rr++) { vbuf2[rr] = __expf(vbuf2[rr] - m); s += vbuf2[rr]; }
                float inv = SCALE / s;
                #pragma unroll
                for (int rr = 0; rr < 32; rr++)
                    stage[hb * 32 + rr][col] = vbuf2[rr] * inv;
            }
        }
        __syncthreads();
        #pragma unroll
        for (int it = 0; it < 16; it++) {
            int idx = tid + it * 128;
            int r = idx >> 4, c8 = (idx & 15) * 8;
            union { uint4 u; __nv_bfloat162 h2[4]; } o;
            #pragma unroll
            for (int u2 = 0; u2 < 4; u2++)
                o.h2[u2] = __floats2bfloat162_rn(stage[r][c8 + 2 * u2], stage[r][c8 + 2 * u2 + 1]);
            *(uint4*)(g_qt + (size_t)(b * Dm + et * 128 + r) * CT + (size_t)tt * 128 + c8) = o.u;
        }
        return;
    }

    // ---- kv path ----
    {
        float* scr = (float*)(sm + U_SCR) + w * 320;   // [16][20] f32 per warp
        const int r2 = lane >> 1, cb = (lane & 1) * 8;
        #pragma unroll
        for (int i = 0; i < 4; i++) {
            int row = i * 16 + r2;
            float bsv = biasT[wm * 64 + row];
            float rowsum = 0.f;
            #pragma unroll
            for (int j = 0; j < 4; j++) {
                wmma::store_matrix_sync(scr, acc[i][j], 20, wmma::mem_row_major);
                __syncwarp();
                union { uint4 u; __nv_bfloat162 h2[4]; } o;
                if (wm == 0) {
                    #pragma unroll
                    for (int u = 0; u < 4; u++) {
                        float e0 = __expf(scr[r2 * 20 + cb + 2 * u] + bsv);
                        float e1 = __expf(scr[r2 * 20 + cb + 2 * u + 1] + bsv);
                        rowsum += e0 + e1;
                        o.h2[u] = __floats2bfloat162_rn(e0, e1);
                    }
                    *(uint4*)&kbuf[row][wn * 64 + j * 16 + cb] = o.u;
                } else {
                    #pragma unroll
                    for (int u = 0; u < 4; u++) {
                        float e0 = (scr[r2 * 20 + cb + 2 * u] + bsv) * (1.0f / 1024.0f);
                        float e1 = (scr[r2 * 20 + cb + 2 * u + 1] + bsv) * (1.0f / 1024.0f);
                        o.h2[u] = __floats2bfloat162_rn(e0, e1);
                    }
                    *(uint4*)&vbuf[row][wn * 64 + j * 16 + cb] = o.u;
                }
                __syncwarp();
            }
            if (wm == 0) {
                rowsum += __shfl_xor_sync(~0u, rowsum, 1);
                if ((lane & 1) == 0) S_s[wn * 64 + row] = rowsum;
            }
        }
    }
    __syncthreads();

    const int c = tt >> 3, slot = tt & 7;
    const int bc = b * Cc + c;

    {
        int hl = w >> 1, th = w & 1;
        wmma::fragment<wmma::accumulator, 16, 16, 16, float> ca[2][2];
        #pragma unroll
        for (int i = 0; i < 2; i++)
            #pragma unroll
            for (int j = 0; j < 2; j++) wmma::fill_fragment(ca[i][j], 0.f);
        #pragma unroll
        for (int kk = 0; kk < 64; kk += 16) {
            wmma::fragment<wmma::matrix_a, 16, 16, 16, bf, wmma::row_major> af;
            wmma::fragment<wmma::matrix_b, 16, 16, 16, bf, wmma::col_major> bv;
            #pragma unroll
            for (int i = 0; i < 2; i++) {
                wmma::load_matrix_sync(af, &kbuf[hl * 32 + i * 16][th * 64 + kk], 136);
                #pragma unroll
                for (int j = 0; j < 2; j++) {
                    wmma::load_matrix_sync(bv, &vbuf[hl * 32 + j * 16][th * 64 + kk], 136);
                    wmma::mma_sync(ca[i][j], af, bv, ca[i][j]);
                }
            }
        }
        __syncthreads();
        float* hst = (float*)(sm + U_HST) + hl * 1280;   // [32][40]
        if (th == 1) {
            #pragma unroll
            for (int i = 0; i < 2; i++)
                #pragma unroll
                for (int j = 0; j < 2; j++)
                    wmma::store_matrix_sync(&hst[(i * 16) * 40 + j * 16],
                                            ca[i][j], 40, wmma::mem_row_major);
        }
        __syncthreads();
        if (th == 0) {
            float* dst = g_ctxp + (((size_t)bc * 8 + slot) * Hh + hp * 2 + hl) * 1024;
            wmma::fragment<wmma::accumulator, 16, 16, 16, float> tmp;
            #pragma unroll
            for (int i = 0; i < 2; i++)
                #pragma unroll
                for (int j = 0; j < 2; j++) {
                    wmma::load_matrix_sync(tmp, &hst[(i * 16) * 40 + j * 16],
                                           40, wmma::mem_row_major);
                    for (int e = 0; e < tmp.num_elements; e++) ca[i][j].x[e] += tmp.x[e];
                    wmma::store_matrix_sync(dst + (i * 16) * 32 + j * 16,
                                            ca[i][j], 32, wmma::mem_row_major);
                }
        }
    }
    if (tid < 64)
        g_Sp[((size_t)bc * 8 + slot) * 256 + hp * 64 + tid] = S_s[tid] + S_s[64 + tid];
}

// ---------------- K4: Mcat = W_out x blockdiag(ctx^T/S), reducing 8 slots ----------------
__global__ __launch_bounds__(256) void mcat_kernel() {
    int bc = blockIdx.x;
    __shared__ float Ssum[256];
    __shared__ bf ctxs[8192];
    int tid = threadIdx.x;
    {
        float s = 0.f;
        #pragma unroll
        for (int sl = 0; sl < 8; sl++)
            s += g_Sp[((size_t)bc * 8 + sl) * 256 + tid];
        Ssum[tid] = s;
    }
    __syncthreads();
    for (int i = tid; i < 8192; i += 256) {
        int h = i >> 10, fk = (i >> 5) & 31, fv = i & 31;
        float v = 0.f;
        #pragma unroll
        for (int sl = 0; sl < 8; sl++)
            v += g_ctxp[(((size_t)bc * 8 + sl) * Hh + h) * 1024 + fk * 32 + fv];
        ctxs[h * 1024 + fv * 32 + fk] = __float2bfloat16(v / Ssum[h * 32 + fk]);
    }
    __syncthreads();
    int e = tid;
    const bf* wrow = g_wout + e * Dm;
    #pragma unroll 1
    for (int h = 0; h < 8; h++) {
        float wv[32];
        #pragma unroll
        for (int fv = 0; fv < 32; fv++) wv[fv] = __bfloat162float(wrow[h * 32 + fv]);
        float o[32];
        #pragma unroll
        for (int fk = 0; fk < 32; fk++) o[fk] = 0.f;
        #pragma unroll
        for (int fv = 0; fv < 32; fv++) {
            float wf = wv[fv];
            const bf* cr = ctxs + h * 1024 + fv * 32;
            #pragma unroll
            for (int fk = 0; fk < 32; fk++) o[fk] += wf * __bfloat162float(cr[fk]);
        }
        __align__(16) bf ob[32];
        #pragma unroll
        for (int fk = 0; fk < 32; fk++) ob[fk] = __float2bfloat16(o[fk]);
        uint4* dst = (uint4*)(g_mcat + ((size_t)bc * Dm + e) * Dm + h * 32);
        const uint4* src = (const uint4*)ob;
        #pragma unroll
        for (int q2 = 0; q2 < 4; q2++) dst[q2] = src[q2];
    }
}

// ---------------- K5: out = Mcat[bc] @ q~ + out_b + x (4-warp 64x64 3-stage) ----------------
#define FG_SB    55296
#define FG_SBIAS 107520
#define FG_SMEM  108032

__global__ __launch_bounds__(128) void final_gemm(const float* __restrict__ x,
                                                  const float* __restrict__ out_b,
                                                  float* __restrict__ out) {
    extern __shared__ __align__(16) char sm[];
    bf (*A_s)[128][72] = (bf(*)[128][72])sm;
    bf (*B_s)[64][136] = (bf(*)[64][136])(sm + FG_SB);
    float (*stage)[132] = (float(*)[132])sm;
    float* biasO = (float*)(sm + FG_SBIAS);

    const int bx = blockIdx.x;   // t tile (8)
    const int by = blockIdx.y;   // e half (2)
    const int bc = blockIdx.z;   // 128
    const int b = bc >> 6, c = bc & 63;

    const int tid = threadIdx.x;
    const int w = tid >> 5;
    const int wm = w >> 1, wn = w & 1;

    biasO[tid] = out_b[by * 128 + tid];

    const bf* Aptr = g_mcat + (size_t)bc * Dm * Dm + (size_t)by * 128 * Dm;
    const bf* Bptr = g_qt + (size_t)b * Dm * CT + (size_t)c * Tt + (size_t)bx * 128;

    wmma::fragment<wmma::accumulator, 16, 16, 16, float> acc[4][4];
    #pragma unroll
    for (int i = 0; i < 4; i++)
        #pragma unroll
        for (int j = 0; j < 4; j++) wmma::fill_fragment(acc[i][j], 0.0f);

    auto loadA = [&](int s, int k0) {
        #pragma unroll
        for (int it = 0; it < 8; it++) {
            int idx = tid + it * 128;
            int r = idx >> 3, c8 = (idx & 7) * 8;
            cp16(&A_s[s][r][c8], Aptr + (size_t)r * Dm + k0 + c8);
        }
    };
    auto loadB = [&](int s, int k0) {
        #pragma unroll
        for (int it = 0; it < 8; it++) {
            int idx = tid + it * 128;
            int r = idx >> 4, c8 = (idx & 15) * 8;
            cp16(&B_s[s][r][c8], Bptr + (size_t)(k0 + r) * CT + c8);
        }
    };
    auto mma_chunk = [&](int st) {
        #pragma unroll
        for (int kk = 0; kk < 64; kk += 16) {
            wmma::fragment<wmma::matrix_a, 16, 16, 16, bf, wmma::row_major> af[4];
            wmma::fragment<wmma::matrix_b, 16, 16, 16, bf, wmma::row_major> bfr[4];
            #pragma unroll
            for (int i = 0; i < 4; i++)
                wmma::load_matrix_sync(af[i], &A_s[st][wm * 64 + i * 16][kk], 72);
            #pragma unroll
            for (int j = 0; j < 4; j++)
                wmma::load_matrix_sync(bfr[j], &B_s[st][kk][wn * 64 + j * 16], 136);
            #pragma unroll
            for (int i = 0; i < 4; i++)
                #pragma unroll
                for (int j = 0; j < 4; j++)
                    wmma::mma_sync(acc[i][j], af[i], bfr[j], acc[i][j]);
        }
    };

    loadA(0, 0);   loadB(0, 0);   CP_COMMIT();
    loadA(1, 64);  loadB(1, 64);  CP_COMMIT();
    CP_WAIT1(); __syncthreads();
    mma_chunk(0);
    loadA(2, 128); loadB(2, 128); CP_COMMIT();
    CP_WAIT1(); __syncthreads();
    mma_chunk(1);
    loadA(0, 192); loadB(0, 192); CP_COMMIT();
    CP_WAIT1(); __syncthreads();
    mma_chunk(2);
    CP_WAIT0(); __syncthreads();
    mma_chunk(0);
    __syncthreads();

    #pragma unroll
    for (int i = 0; i < 4; i++)
        #pragma unroll
        for (int j = 0; j < 4; j++)
            wmma::store_matrix_sync(&stage[wm * 64 + i * 16][wn * 64 + j * 16],
                                    acc[i][j], 132, wmma::mem_row_major);
    __syncthreads();

    #pragma unroll
    for (int it = 0; it < 32; it++) {
        int idx = tid + it * 128;
        int r = idx >> 5, c4 = (idx & 31) * 4;
        int e = by * 128 + r;
        size_t gi = ((size_t)(b * Dm + e) * Cc + c) * Tt + (size_t)bx * 128 + c4;
        float4 xv = *(const float4*)(x + gi);
        float bo = biasO[r];
        float4 o;
        o.x = stage[r][c4 + 0] + bo + xv.x;
        o.y = stage[r][c4 + 1] + bo + xv.y;
        o.z = stage[r][c4 + 2] + bo + xv.z;
        o.w = stage[r][c4 + 3] + bo + xv.w;
        *(float4*)(out + gi) = o;
    }
}

// ---------------- launch ----------------
extern "C" void kernel_launch(void* const* d_in, const int* in_sizes, int n_in,
                              void* d_out, int out_size) {
    const float* x     = (const float*)d_in[0];
    const float* in_w  = (const float*)d_in[1];
    const float* in_b  = (const float*)d_in[2];
    const float* out_w = (const float*)d_in[3];
    const float* out_b = (const float*)d_in[4];
    float* out = (float*)d_out;

    cudaFuncSetAttribute(qkv_unified, cudaFuncAttributeMaxDynamicSharedMemorySize, U_SMEM);
    cudaFuncSetAttribute(final_gemm, cudaFuncAttributeMaxDynamicSharedMemorySize, FG_SMEM);

    stats_cvt<<<Bn * Dm, 256>>>(x);
    prep_weights<<<Bn * E3, 256>>>(in_w, in_b);
    conv_outw<<<Dm * Dm / 256, 256>>>(out_w);
    qkv_unified<<<dim3(6, CT / 128, Bn), 128, U_SMEM>>>();
    mcat_kernel<<<Bn * Cc, 256>>>();
    final_gemm<<<dim3(Tt / 128, 2, Bn * Cc), 128, FG_SMEM>>>(x, out_b, out);
}

// round 15
// speedup vs baseline: 1.0392x; 1.0392x over previous
#include <cstdint>
#include <cuda_runtime.h>
#include <cuda_bf16.h>
#include <mma.h>

using namespace nvcuda;
typedef __nv_bfloat16 bf;

#define Bn 2
#define Dm 256
#define Cc 64
#define Tt 1024
#define Hh 8
#define Ff 32
#define CT 65536
#define E3 768
#define EPS 1e-5f
#define SCALE 0.1767766952966369f

// ---------------- scratch ----------------
__device__ __align__(128) bf g_xbf[(size_t)Bn * Dm * CT];      // 67 MB
__device__ __align__(128) bf g_qt[(size_t)Bn * Dm * CT];       // q~ only
__device__ __align__(128) bf g_weff[(size_t)Bn * E3 * Dm];
__device__ float g_mu[Bn * Dm];
__device__ float g_rstd[Bn * Dm];
__device__ float g_bias[Bn * E3];
__device__ __align__(128) bf g_wout[Dm * Dm];
__device__ __align__(128) float g_ctxp[(size_t)Bn * Cc * 8 * Hh * Ff * Ff];
__device__ __align__(128) float g_Sp[(size_t)Bn * Cc * 8 * 256];
__device__ __align__(128) bf g_mcat[(size_t)Bn * Cc * Dm * Dm];

// ---------------- cp.async ----------------
__device__ __forceinline__ void cp16(void* smem, const void* gmem) {
    unsigned s = (unsigned)__cvta_generic_to_shared(smem);
    asm volatile("cp.async.cg.shared.global [%0], [%1], 16;\n" :: "r"(s), "l"(gmem));
}
#define CP_COMMIT() asm volatile("cp.async.commit_group;\n")
#define CP_WAIT1()  asm volatile("cp.async.wait_group 1;\n")
#define CP_WAIT0()  asm volatile("cp.async.wait_group 0;\n")

// ---------------- K1: stats + convert x to bf16 ----------------
__global__ __launch_bounds__(256) void stats_cvt(const float* __restrict__ x) {
    size_t base = (size_t)blockIdx.x * CT;
    const float4* p = (const float4*)(x + base);
    bf* ob = g_xbf + base;
    float s = 0.f, ss = 0.f;
    for (int i = threadIdx.x; i < CT / 4; i += 256) {
        float4 v = p[i];
        s += v.x + v.y + v.z + v.w;
        ss += v.x * v.x + v.y * v.y + v.z * v.z + v.w * v.w;
        union { uint2 u; __nv_bfloat162 h[2]; } pk;
        pk.h[0] = __floats2bfloat162_rn(v.x, v.y);
        pk.h[1] = __floats2bfloat162_rn(v.z, v.w);
        *(uint2*)(ob + (size_t)i * 4) = pk.u;
    }
    __shared__ float rs[8], rss[8];
    for (int off = 16; off; off >>= 1) {
        s  += __shfl_down_sync(~0u, s, off);
        ss += __shfl_down_sync(~0u, ss, off);
    }
    int wid = threadIdx.x >> 5, lane = threadIdx.x & 31;
    if (lane == 0) { rs[wid] = s; rss[wid] = ss; }
    __syncthreads();
    if (threadIdx.x == 0) {
        float S = 0.f, SS = 0.f;
        for (int i = 0; i < 8; i++) { S += rs[i]; SS += rss[i]; }
        float mu = S / (float)CT;
        float var = SS / (float)CT - mu * mu;
        g_mu[blockIdx.x] = mu;
        g_rstd[blockIdx.x] = rsqrtf(var + EPS);
    }
}

// ---------------- K2: fold instance norm into weights ----------------
__global__ __launch_bounds__(256) void prep_weights(const float* __restrict__ in_w,
                                                    const float* __restrict__ in_b) {
    int be = blockIdx.x;
    int b = be / E3, e = be % E3;
    int d = threadIdx.x;
    float w = in_w[e * Dm + d];
    float r = g_rstd[b * Dm + d];
    float m = g_mu[b * Dm + d];
    float we = w * r;
    g_weff[(size_t)be * Dm + d] = __float2bfloat16(we);
    __shared__ float red[256];
    red[d] = we * m;
    __syncthreads();
    for (int s = 128; s > 0; s >>= 1) {
        if (d < s) red[d] += red[d + s];
        __syncthreads();
    }
    if (d == 0) g_bias[be] = in_b[e] - red[0];
}

__global__ __launch_bounds__(256) void conv_outw(const float* __restrict__ out_w) {
    int i = blockIdx.x * 256 + threadIdx.x;
    g_wout[i] = __float2bfloat16(out_w[i]);
}

// ---------------- K3a: q GEMM, 128 thr, 64x64 warp tiles, 3-stage, softmax epi ----------------
#define QG_SB    55296
#define QG_SBIAS 107520
#define QG_SMEM  108032

__global__ __launch_bounds__(128) void q_gemm() {
    extern __shared__ __align__(16) char sm[];
    bf (*A_s)[128][72] = (bf(*)[128][72])sm;
    bf (*B_s)[64][136] = (bf(*)[64][136])(sm + QG_SB);
    float (*stage)[132] = (float(*)[132])sm;
    float* biasT = (float*)(sm + QG_SBIAS);

    const int et = blockIdx.x;   // 0..1 (q rows et*128)
    const int tt = blockIdx.y;
    const int b  = blockIdx.z;

    const int tid = threadIdx.x;
    const int w = tid >> 5;
    const int wm = w >> 1, wn = w & 1;

    biasT[tid] = g_bias[b * E3 + et * 128 + tid];

    const bf* Aptr = g_weff + (size_t)(b * E3 + et * 128) * Dm;
    const bf* Bptr = g_xbf + (size_t)b * Dm * CT + (size_t)tt * 128;

    wmma::fragment<wmma::accumulator, 16, 16, 16, float> acc[4][4];
    #pragma unroll
    for (int i = 0; i < 4; i++)
        #pragma unroll
        for (int j = 0; j < 4; j++) wmma::fill_fragment(acc[i][j], 0.0f);

    auto loadA = [&](int s, int k0) {
        #pragma unroll
        for (int it = 0; it < 8; it++) {
            int idx = tid + it * 128;
            int r = idx >> 3, c8 = (idx & 7) * 8;
            cp16(&A_s[s][r][c8], Aptr + (size_t)r * Dm + k0 + c8);
        }
    };
    auto loadB = [&](int s, int k0) {
        #pragma unroll
        for (int it = 0; it < 8; it++) {
            int idx = tid + it * 128;
            int r = idx >> 4, c8 = (idx & 15) * 8;
            cp16(&B_s[s][r][c8], Bptr + (size_t)(k0 + r) * CT + c8);
        }
    };
    auto mma_chunk = [&](int st) {
        #pragma unroll
        for (int kk = 0; kk < 64; kk += 16) {
            wmma::fragment<wmma::matrix_a, 16, 16, 16, bf, wmma::row_major> af[4];
            wmma::fragment<wmma::matrix_b, 16, 16, 16, bf, wmma::row_major> bfr[4];
            #pragma unroll
            for (int i = 0; i < 4; i++)
                wmma::load_matrix_sync(af[i], &A_s[st][wm * 64 + i * 16][kk], 72);
            #pragma unroll
            for (int j = 0; j < 4; j++)
                wmma::load_matrix_sync(bfr[j], &B_s[st][kk][wn * 64 + j * 16], 136);
            #pragma unroll
            for (int i = 0; i < 4; i++)
                #pragma unroll
                for (int j = 0; j < 4; j++)
                    wmma::mma_sync(acc[i][j], af[i], bfr[j], acc[i][j]);
        }
    };

    loadA(0, 0);   loadB(0, 0);   CP_COMMIT();
    loadA(1, 64);  loadB(1, 64);  CP_COMMIT();
    CP_WAIT1(); __syncthreads();
    mma_chunk(0);
    loadA(2, 128); loadB(2, 128); CP_COMMIT();
    CP_WAIT1(); __syncthreads();
    mma_chunk(1);
    loadA(0, 192); loadB(0, 192); CP_COMMIT();
    CP_WAIT1(); __syncthreads();
    mma_chunk(2);
    CP_WAIT0(); __syncthreads();
    mma_chunk(0);
    __syncthreads();

    #pragma unroll
    for (int i = 0; i < 4; i++)
        #pragma unroll
        for (int j = 0; j < 4; j++)
            wmma::store_matrix_sync(&stage[wm * 64 + i * 16][wn * 64 + j * 16],
                                    acc[i][j], 132, wmma::mem_row_major);
    __syncthreads();

    {   // column softmax per 32-row head block (4 blocks); bias folded here
        int col = tid;
        #pragma unroll
        for (int hb = 0; hb < 4; hb++) {
            float vbuf[32];
            float m = -1e30f;
            #pragma unroll
            for (int rr = 0; rr < 32; rr++) {
                float vv = stage[hb * 32 + rr][col] + biasT[hb * 32 + rr];
                vbuf[rr] = vv; m = fmaxf(m, vv);
            }
            float s = 0.f;
            #pragma unroll
            for (int rr = 0; rr < 32; rr++) { vbuf[rr] = __expf(vbuf[rr] - m); s += vbuf[rr]; }
            float inv = SCALE / s;
            #pragma unroll
            for (int rr = 0; rr < 32; rr++)
                stage[hb * 32 + rr][col] = vbuf[rr] * inv;
        }
    }
    __syncthreads();
    #pragma unroll
    for (int it = 0; it < 16; it++) {
        int idx = tid + it * 128;
        int r = idx >> 4, c8 = (idx & 15) * 8;
        union { uint4 u; __nv_bfloat162 h2[4]; } o;
        #pragma unroll
        for (int u2 = 0; u2 < 4; u2++)
            o.h2[u2] = __floats2bfloat162_rn(stage[r][c8 + 2 * u2], stage[r][c8 + 2 * u2 + 1]);
        *(uint4*)(g_qt + (size_t)(b * Dm + et * 128 + r) * CT + (size_t)tt * 128 + c8) = o.u;
    }
}

// ---------------- K3b: kv GEMM, A resident, 2 t-tiles/block, fused exp/ctx ----------------
// Block = (head pair hp, t-group of 2 tiles, b). A_res loaded once.
// smem: A_res[128][264] @0 (67584), B[2][64][136] @67584 (34816),
//   overlays on B: kbuf[64][136] @67584, vbuf @84992.
//   biasT @102400 (512), S_s @102912 (512),
//   scr (4 warps x [16][20] f32 = 5120) and hstage (2 x [32][36] f32 = 9216)
//   share @103424 (union, different phases). total 112640 -> 2 CTAs/SM.
#define KV_B     67584
#define KV_KB    67584
#define KV_VB    84992
#define KV_BIAS  102400
#define KV_SS    102912
#define KV_SCR   103424
#define KV_HST   103424
#define KV_SMEM  112640

__global__ __launch_bounds__(128) void kv_fused() {
    extern __shared__ __align__(16) char sm[];
    bf (*A_res)[264] = (bf(*)[264])sm;
    bf (*B_s)[64][136] = (bf(*)[64][136])(sm + KV_B);
    bf (*kbuf)[136] = (bf(*)[136])(sm + KV_KB);
    bf (*vbuf)[136] = (bf(*)[136])(sm + KV_VB);
    float* biasT = (float*)(sm + KV_BIAS);
    float* S_s   = (float*)(sm + KV_SS);

    const int hp = blockIdx.x;   // head pair 0..3
    const int tg = blockIdx.y;   // 256 t-groups (2 tiles each)
    const int b  = blockIdx.z;

    const int tid = threadIdx.x;
    const int w = tid >> 5, lane = tid & 31;
    const int wm = w >> 1, wn = w & 1;

    auto rowmap = [&](int r) {
        return r < 64 ? (256 + hp * 64 + r) : (512 + hp * 64 + r - 64);
    };
    biasT[tid] = g_bias[b * E3 + rowmap(tid)];

    const bf* Wb = g_weff + (size_t)b * E3 * Dm;

    // load A once (128 x 256 bf16 into [128][264])
    #pragma unroll
    for (int it = 0; it < 32; it++) {
        int idx = tid + it * 128;
        int r = idx >> 5, c8 = (idx & 31) * 8;
        cp16(&A_res[r][c8], Wb + (size_t)rowmap(r) * Dm + c8);
    }
    CP_COMMIT();

    for (int ti = 0; ti < 2; ti++) {
        const int tt = tg * 2 + ti;
        const bf* Bptr = g_xbf + (size_t)b * Dm * CT + (size_t)tt * 128;

        wmma::fragment<wmma::accumulator, 16, 16, 16, float> acc[4][4];
        #pragma unroll
        for (int i = 0; i < 4; i++)
            #pragma unroll
            for (int j = 0; j < 4; j++) wmma::fill_fragment(acc[i][j], 0.0f);

        auto loadB = [&](int s, int k0) {
            #pragma unroll
            for (int it = 0; it < 8; it++) {
                int idx = tid + it * 128;
                int r = idx >> 4, c8 = (idx & 15) * 8;
                cp16(&B_s[s][r][c8], Bptr + (size_t)(k0 + r) * CT + c8);
            }
        };
        auto mma_chunk = [&](int st, int k0) {
            #pragma unroll
            for (int kk = 0; kk < 64; kk += 16) {
                wmma::fragment<wmma::matrix_a, 16, 16, 16, bf, wmma::row_major> af[4];
                wmma::fragment<wmma::matrix_b, 16, 16, 16, bf, wmma::row_major> bfr[4];
                #pragma unroll
                for (int i = 0; i < 4; i++)
                    wmma::load_matrix_sync(af[i], &A_res[wm * 64 + i * 16][k0 + kk], 264);
                #pragma unroll
                for (int j = 0; j < 4; j++)
                    wmma::load_matrix_sync(bfr[j], &B_s[st][kk][wn * 64 + j * 16], 136);
                #pragma unroll
                for (int i = 0; i < 4; i++)
                    #pragma unroll
                    for (int j = 0; j < 4; j++)
                        wmma::mma_sync(acc[i][j], af[i], bfr[j], acc[i][j]);
            }
        };

        loadB(0, 0);  CP_COMMIT();
        loadB(1, 64); CP_COMMIT();
        CP_WAIT1(); __syncthreads();       // A (ti=0) + B0 ready
        mma_chunk(0, 0);
        __syncthreads();
        loadB(0, 128); CP_COMMIT();
        CP_WAIT1(); __syncthreads();
        mma_chunk(1, 64);
        __syncthreads();
        loadB(1, 192); CP_COMMIT();
        CP_WAIT1(); __syncthreads();
        mma_chunk(0, 128);
        CP_WAIT0(); __syncthreads();
        mma_chunk(1, 192);
        __syncthreads();   // B buffers dead; kbuf/vbuf overlays live

        // epilogue via per-warp scratch: wm=0 -> exp -> kbuf (+S), wm=1 -> /T -> vbuf
        {
            float* scr = (float*)(sm + KV_SCR) + w * 320;   // [16][20] f32
            const int r2 = lane >> 1, cb = (lane & 1) * 8;
            #pragma unroll
            for (int i = 0; i < 4; i++) {
                int row = i * 16 + r2;
                float bsv = biasT[wm * 64 + row];
                float rowsum = 0.f;
                #pragma unroll
                for (int j = 0; j < 4; j++) {
                    wmma::store_matrix_sync(scr, acc[i][j], 20, wmma::mem_row_major);
                    __syncwarp();
                    union { uint4 u; __nv_bfloat162 h2[4]; } o;
                    if (wm == 0) {
                        #pragma unroll
                        for (int u = 0; u < 4; u++) {
                            float e0 = __expf(scr[r2 * 20 + cb + 2 * u] + bsv);
                            float e1 = __expf(scr[r2 * 20 + cb + 2 * u + 1] + bsv);
                            rowsum += e0 + e1;
                            o.h2[u] = __floats2bfloat162_rn(e0, e1);
                        }
                        *(uint4*)&kbuf[row][wn * 64 + j * 16 + cb] = o.u;
                    } else {
                        #pragma unroll
                        for (int u = 0; u < 4; u++) {
                            float e0 = (scr[r2 * 20 + cb + 2 * u] + bsv) * (1.0f / 1024.0f);
                            float e1 = (scr[r2 * 20 + cb + 2 * u + 1] + bsv) * (1.0f / 1024.0f);
                            o.h2[u] = __floats2bfloat162_rn(e0, e1);
                        }
                        *(uint4*)&vbuf[row][wn * 64 + j * 16 + cb] = o.u;
                    }
                    __syncwarp();
                }
                if (wm == 0) {
                    rowsum += __shfl_xor_sync(~0u, rowsum, 1);
                    if ((lane & 1) == 0) S_s[wn * 64 + row] = rowsum;
                }
            }
        }
        __syncthreads();

        const int c = tt >> 3, slot = tt & 7;
        const int bc = b * Cc + c;

        // ctx: warp (hl = head local, th = t half)
        {
            int hl = w >> 1, th = w & 1;
            wmma::fragment<wmma::accumulator, 16, 16, 16, float> ca[2][2];
            #pragma unroll
            for (int i = 0; i < 2; i++)
                #pragma unroll
                for (int j = 0; j < 2; j++) wmma::fill_fragment(ca[i][j], 0.f);
            #pragma unroll
            for (int kk = 0; kk < 64; kk += 16) {
                wmma::fragment<wmma::matrix_a, 16, 16, 16, bf, wmma::row_major> af;
                wmma::fragment<wmma::matrix_b, 16, 16, 16, bf, wmma::col_major> bv;
                #pragma unroll
                for (int i = 0; i < 2; i++) {
                    wmma::load_matrix_sync(af, &kbuf[hl * 32 + i * 16][th * 64 + kk], 136);
                    #pragma unroll
                    for (int j = 0; j < 2; j++) {
                        wmma::load_matrix_sync(bv, &vbuf[hl * 32 + j * 16][th * 64 + kk], 136);
                        wmma::mma_sync(ca[i][j], af, bv, ca[i][j]);
                    }
                }
            }
            __syncthreads();
            float* hst = (float*)(sm + KV_HST) + hl * 1152;   // [32][36]
            if (th == 1) {
                #pragma unroll
                for (int i = 0; i < 2; i++)
                    #pragma unroll
                    for (int j = 0; j < 2; j++)
                        wmma::store_matrix_sync(&hst[(i * 16) * 36 + j * 16],
                                                ca[i][j], 36, wmma::mem_row_major);
            }
            __syncthreads();
            if (th == 0) {
                float* dst = g_ctxp + (((size_t)bc * 8 + slot) * Hh + hp * 2 + hl) * 1024;
                wmma::fragment<wmma::accumulator, 16, 16, 16, float> tmp;
                #pragma unroll
                for (int i = 0; i < 2; i++)
                    #pragma unroll
                    for (int j = 0; j < 2; j++) {
                        wmma::load_matrix_sync(tmp, &hst[(i * 16) * 36 + j * 16],
                                               36, wmma::mem_row_major);
                        for (int e = 0; e < tmp.num_elements; e++) ca[i][j].x[e] += tmp.x[e];
                        wmma::store_matrix_sync(dst + (i * 16) * 32 + j * 16,
                                                ca[i][j], 32, wmma::mem_row_major);
                    }
            }
        }
        if (tid < 64)
            g_Sp[((size_t)bc * 8 + slot) * 256 + hp * 64 + tid] = S_s[tid] + S_s[64 + tid];
        __syncthreads();   // S_s/kbuf reads complete before next iteration
    }
}

// ---------------- K4: Mcat = W_out x blockdiag(ctx^T/S), reducing 8 slots ----------------
__global__ __launch_bounds__(256) void mcat_kernel() {
    int bc = blockIdx.x;
    __shared__ float Ssum[256];
    __shared__ bf ctxs[8192];
    int tid = threadIdx.x;
    {
        float s = 0.f;
        #pragma unroll
        for (int sl = 0; sl < 8; sl++)
            s += g_Sp[((size_t)bc * 8 + sl) * 256 + tid];
        Ssum[tid] = s;
    }
    __syncthreads();
    for (int i = tid; i < 8192; i += 256) {
        int h = i >> 10, fk = (i >> 5) & 31, fv = i & 31;
        float v = 0.f;
        #pragma unroll
        for (int sl = 0; sl < 8; sl++)
            v += g_ctxp[(((size_t)bc * 8 + sl) * Hh + h) * 1024 + fk * 32 + fv];
        ctxs[h * 1024 + fv * 32 + fk] = __float2bfloat16(v / Ssum[h * 32 + fk]);
    }
    __syncthreads();
    int e = tid;
    const bf* wrow = g_wout + e * Dm;
    #pragma unroll 1
    for (int h = 0; h < 8; h++) {
        float wv[32];
        #pragma unroll
        for (int fv = 0; fv < 32; fv++) wv[fv] = __bfloat162float(wrow[h * 32 + fv]);
        float o[32];
        #pragma unroll
        for (int fk = 0; fk < 32; fk++) o[fk] = 0.f;
        #pragma unroll
        for (int fv = 0; fv < 32; fv++) {
            float wf = wv[fv];
            const bf* cr = ctxs + h * 1024 + fv * 32;
            #pragma unroll
            for (int fk = 0; fk < 32; fk++) o[fk] += wf * __bfloat162float(cr[fk]);
        }
        __align__(16) bf ob[32];
        #pragma unroll
        for (int fk = 0; fk < 32; fk++) ob[fk] = __float2bfloat16(o[fk]);
        uint4* dst = (uint4*)(g_mcat + ((size_t)bc * Dm + e) * Dm + h * 32);
        const uint4* src = (const uint4*)ob;
        #pragma unroll
        for (int q2 = 0; q2 < 4; q2++) dst[q2] = src[q2];
    }
}

// ---------------- K5: out = Mcat[bc] @ q~ + out_b + x (4-warp 64x64 3-stage) ----------------
#define FG_SB    55296
#define FG_SBIAS 107520
#define FG_SMEM  108032

__global__ __launch_bounds__(128) void final_gemm(const float* __restrict__ x,
                                                  const float* __restrict__ out_b,
                                                  float* __restrict__ out) {
    extern __shared__ __align__(16) char sm[];
    bf (*A_s)[128][72] = (bf(*)[128][72])sm;
    bf (*B_s)[64][136] = (bf(*)[64][136])(sm + FG_SB);
    float (*stage)[132] = (float(*)[132])sm;
    float* biasO = (float*)(sm + FG_SBIAS);

    const int bx = blockIdx.x;   // t tile (8)
    const int by = blockIdx.y;   // e half (2)
    const int bc = blockIdx.z;   // 128
    const int b = bc >> 6, c = bc & 63;

    const int tid = threadIdx.x;
    const int w = tid >> 5;
    const int wm = w >> 1, wn = w & 1;

    biasO[tid] = out_b[by * 128 + tid];

    const bf* Aptr = g_mcat + (size_t)bc * Dm * Dm + (size_t)by * 128 * Dm;
    const bf* Bptr = g_qt + (size_t)b * Dm * CT + (size_t)c * Tt + (size_t)bx * 128;

    wmma::fragment<wmma::accumulator, 16, 16, 16, float> acc[4][4];
    #pragma unroll
    for (int i = 0; i < 4; i++)
        #pragma unroll
        for (int j = 0; j < 4; j++) wmma::fill_fragment(acc[i][j], 0.0f);

    auto loadA = [&](int s, int k0) {
        #pragma unroll
        for (int it = 0; it < 8; it++) {
            int idx = tid + it * 128;
            int r = idx >> 3, c8 = (idx & 7) * 8;
            cp16(&A_s[s][r][c8], Aptr + (size_t)r * Dm + k0 + c8);
        }
    };
    auto loadB = [&](int s, int k0) {
        #pragma unroll
        for (int it = 0; it < 8; it++) {
            int idx = tid + it * 128;
            int r = idx >> 4, c8 = (idx & 15) * 8;
            cp16(&B_s[s][r][c8], Bptr + (size_t)(k0 + r) * CT + c8);
        }
    };
    auto mma_chunk = [&](int st) {
        #pragma unroll
        for (int kk = 0; kk < 64; kk += 16) {
            wmma::fragment<wmma::matrix_a, 16, 16, 16, bf, wmma::row_major> af[4];
            wmma::fragment<wmma::matrix_b, 16, 16, 16, bf, wmma::row_major> bfr[4];
            #pragma unroll
            for (int i = 0; i < 4; i++)
                wmma::load_matrix_sync(af[i], &A_s[st][wm * 64 + i * 16][kk], 72);
            #pragma unroll
            for (int j = 0; j < 4; j++)
                wmma::load_matrix_sync(bfr[j], &B_s[st][kk][wn * 64 + j * 16], 136);
            #pragma unroll
            for (int i = 0; i < 4; i++)
                #pragma unroll
                for (int j = 0; j < 4; j++)
                    wmma::mma_sync(acc[i][j], af[i], bfr[j], acc[i][j]);
        }
    };

    loadA(0, 0);   loadB(0, 0);   CP_COMMIT();
    loadA(1, 64);  loadB(1, 64);  CP_COMMIT();
    CP_WAIT1(); __syncthreads();
    mma_chunk(0);
    loadA(2, 128); loadB(2, 128); CP_COMMIT();
    CP_WAIT1(); __syncthreads();
    mma_chunk(1);
    loadA(0, 192); loadB(0, 192); CP_COMMIT();
    CP_WAIT1(); __syncthreads();
    mma_chunk(2);
    CP_WAIT0(); __syncthreads();
    mma_chunk(0);
    __syncthreads();

    #pragma unroll
    for (int i = 0; i < 4; i++)
        #pragma unroll
        for (int j = 0; j < 4; j++)
            wmma::store_matrix_sync(&stage[wm * 64 + i * 16][wn * 64 + j * 16],
                                    acc[i][j], 132, wmma::mem_row_major);
    __syncthreads();

    #pragma unroll
    for (int it = 0; it < 32; it++) {
        int idx = tid + it * 128;
        int r = idx >> 5, c4 = (idx & 31) * 4;
        int e = by * 128 + r;
        size_t gi = ((size_t)(b * Dm + e) * Cc + c) * Tt + (size_t)bx * 128 + c4;
        float4 xv = *(const float4*)(x + gi);
        float bo = biasO[r];
        float4 o;
        o.x = stage[r][c4 + 0] + bo + xv.x;
        o.y = stage[r][c4 + 1] + bo + xv.y;
        o.z = stage[r][c4 + 2] + bo + xv.z;
        o.w = stage[r][c4 + 3] + bo + xv.w;
        *(float4*)(out + gi) = o;
    }
}

// ---------------- launch ----------------
extern "C" void kernel_launch(void* const* d_in, const int* in_sizes, int n_in,
                              void* d_out, int out_size) {
    const float* x     = (const float*)d_in[0];
    const float* in_w  = (const float*)d_in[1];
    const float* in_b  = (const float*)d_in[2];
    const float* out_w = (const float*)d_in[3];
    const float* out_b = (const float*)d_in[4];
    float* out = (float*)d_out;

    cudaFuncSetAttribute(q_gemm, cudaFuncAttributeMaxDynamicSharedMemorySize, QG_SMEM);
    cudaFuncSetAttribute(kv_fused, cudaFuncAttributeMaxDynamicSharedMemorySize, KV_SMEM);
    cudaFuncSetAttribute(final_gemm, cudaFuncAttributeMaxDynamicSharedMemorySize, FG_SMEM);

    stats_cvt<<<Bn * Dm, 256>>>(x);
    prep_weights<<<Bn * E3, 256>>>(in_w, in_b);
    conv_outw<<<Dm * Dm / 256, 256>>>(out_w);
    q_gemm<<<dim3(2, CT / 128, Bn), 128, QG_SMEM>>>();
    kv_fused<<<dim3(4, CT / 256, Bn), 128, KV_SMEM>>>();
    mcat_kernel<<<Bn * Cc, 256>>>();
    final_gemm<<<dim3(Tt / 128, 2, Bn * Cc), 128, FG_SMEM>>>(x, out_b, out);
}

// round 16
// speedup vs baseline: 1.0481x; 1.0085x over previous
#include <cstdint>
#include <cuda_runtime.h>
#include <cuda_bf16.h>
#include <mma.h>

using namespace nvcuda;
typedef __nv_bfloat16 bf;

#define Bn 2
#define Dm 256
#define Cc 64
#define Tt 1024
#define Hh 8
#define Ff 32
#define CT 65536
#define E3 768
#define EPS 1e-5f
#define SCALE 0.1767766952966369f

// ---------------- scratch ----------------
__device__ __align__(128) bf g_xbf[(size_t)Bn * Dm * CT];      // 67 MB
__device__ __align__(128) bf g_qt[(size_t)Bn * Dm * CT];       // q~ only
__device__ __align__(128) bf g_weff[(size_t)Bn * E3 * Dm];
__device__ float g_mu[Bn * Dm];
__device__ float g_rstd[Bn * Dm];
__device__ float g_bias[Bn * E3];
__device__ __align__(128) bf g_wout[Dm * Dm];
__device__ __align__(128) float g_ctxp[(size_t)Bn * Cc * 8 * Hh * Ff * Ff];
__device__ __align__(128) float g_Sp[(size_t)Bn * Cc * 8 * 256];
__device__ __align__(128) bf g_mcat[(size_t)Bn * Cc * Dm * Dm];

// ---------------- cp.async ----------------
__device__ __forceinline__ void cp16(void* smem, const void* gmem) {
    unsigned s = (unsigned)__cvta_generic_to_shared(smem);
    asm volatile("cp.async.cg.shared.global [%0], [%1], 16;\n" :: "r"(s), "l"(gmem));
}
#define CP_COMMIT() asm volatile("cp.async.commit_group;\n")
#define CP_WAIT1()  asm volatile("cp.async.wait_group 1;\n")
#define CP_WAIT0()  asm volatile("cp.async.wait_group 0;\n")

// ---------------- K1: stats + convert x to bf16 ----------------
__global__ __launch_bounds__(256) void stats_cvt(const float* __restrict__ x) {
    size_t base = (size_t)blockIdx.x * CT;
    const float4* p = (const float4*)(x + base);
    bf* ob = g_xbf + base;
    float s = 0.f, ss = 0.f;
    for (int i = threadIdx.x; i < CT / 4; i += 256) {
        float4 v = p[i];
        s += v.x + v.y + v.z + v.w;
        ss += v.x * v.x + v.y * v.y + v.z * v.z + v.w * v.w;
        union { uint2 u; __nv_bfloat162 h[2]; } pk;
        pk.h[0] = __floats2bfloat162_rn(v.x, v.y);
        pk.h[1] = __floats2bfloat162_rn(v.z, v.w);
        *(uint2*)(ob + (size_t)i * 4) = pk.u;
    }
    __shared__ float rs[8], rss[8];
    for (int off = 16; off; off >>= 1) {
        s  += __shfl_down_sync(~0u, s, off);
        ss += __shfl_down_sync(~0u, ss, off);
    }
    int wid = threadIdx.x >> 5, lane = threadIdx.x & 31;
    if (lane == 0) { rs[wid] = s; rss[wid] = ss; }
    __syncthreads();
    if (threadIdx.x == 0) {
        float S = 0.f, SS = 0.f;
        for (int i = 0; i < 8; i++) { S += rs[i]; SS += rss[i]; }
        float mu = S / (float)CT;
        float var = SS / (float)CT - mu * mu;
        g_mu[blockIdx.x] = mu;
        g_rstd[blockIdx.x] = rsqrtf(var + EPS);
    }
}

// ---------------- K2: fold instance norm into weights ----------------
__global__ __launch_bounds__(256) void prep_weights(const float* __restrict__ in_w,
                                                    const float* __restrict__ in_b) {
    int be = blockIdx.x;
    int b = be / E3, e = be % E3;
    int d = threadIdx.x;
    float w = in_w[e * Dm + d];
    float r = g_rstd[b * Dm + d];
    float m = g_mu[b * Dm + d];
    float we = w * r;
    g_weff[(size_t)be * Dm + d] = __float2bfloat16(we);
    __shared__ float red[256];
    red[d] = we * m;
    __syncthreads();
    for (int s = 128; s > 0; s >>= 1) {
        if (d < s) red[d] += red[d + s];
        __syncthreads();
    }
    if (d == 0) g_bias[be] = in_b[e] - red[0];
}

__global__ __launch_bounds__(256) void conv_outw(const float* __restrict__ out_w) {
    int i = blockIdx.x * 256 + threadIdx.x;
    g_wout[i] = __float2bfloat16(out_w[i]);
}

// ---------------- K3a: q GEMM, 128 thr, 64x64 warp tiles, 2-stage (3 CTAs/SM) ----------------
// smem: A[2][128][72] @0 (36864), B[2][64][136] @36864 (34816), biasT @71680 (512).
// stage f32[128][132] (67584) overlays @0. total 72192.
#define QG_SB    36864
#define QG_SBIAS 71680
#define QG_SMEM  72192

__global__ __launch_bounds__(128) void q_gemm() {
    extern __shared__ __align__(16) char sm[];
    bf (*A_s)[128][72] = (bf(*)[128][72])sm;
    bf (*B_s)[64][136] = (bf(*)[64][136])(sm + QG_SB);
    float (*stage)[132] = (float(*)[132])sm;
    float* biasT = (float*)(sm + QG_SBIAS);

    const int et = blockIdx.x;   // 0..1 (q rows et*128)
    const int tt = blockIdx.y;
    const int b  = blockIdx.z;

    const int tid = threadIdx.x;
    const int w = tid >> 5;
    const int wm = w >> 1, wn = w & 1;

    biasT[tid] = g_bias[b * E3 + et * 128 + tid];

    const bf* Aptr = g_weff + (size_t)(b * E3 + et * 128) * Dm;
    const bf* Bptr = g_xbf + (size_t)b * Dm * CT + (size_t)tt * 128;

    wmma::fragment<wmma::accumulator, 16, 16, 16, float> acc[4][4];
    #pragma unroll
    for (int i = 0; i < 4; i++)
        #pragma unroll
        for (int j = 0; j < 4; j++) wmma::fill_fragment(acc[i][j], 0.0f);

    auto loadA = [&](int s, int k0) {
        #pragma unroll
        for (int it = 0; it < 8; it++) {
            int idx = tid + it * 128;
            int r = idx >> 3, c8 = (idx & 7) * 8;
            cp16(&A_s[s][r][c8], Aptr + (size_t)r * Dm + k0 + c8);
        }
    };
    auto loadB = [&](int s, int k0) {
        #pragma unroll
        for (int it = 0; it < 8; it++) {
            int idx = tid + it * 128;
            int r = idx >> 4, c8 = (idx & 15) * 8;
            cp16(&B_s[s][r][c8], Bptr + (size_t)(k0 + r) * CT + c8);
        }
    };
    auto mma_chunk = [&](int st) {
        #pragma unroll
        for (int kk = 0; kk < 64; kk += 16) {
            wmma::fragment<wmma::matrix_a, 16, 16, 16, bf, wmma::row_major> af[4];
            wmma::fragment<wmma::matrix_b, 16, 16, 16, bf, wmma::row_major> bfr[4];
            #pragma unroll
            for (int i = 0; i < 4; i++)
                wmma::load_matrix_sync(af[i], &A_s[st][wm * 64 + i * 16][kk], 72);
            #pragma unroll
            for (int j = 0; j < 4; j++)
                wmma::load_matrix_sync(bfr[j], &B_s[st][kk][wn * 64 + j * 16], 136);
            #pragma unroll
            for (int i = 0; i < 4; i++)
                #pragma unroll
                for (int j = 0; j < 4; j++)
                    wmma::mma_sync(acc[i][j], af[i], bfr[j], acc[i][j]);
        }
    };

    loadA(0, 0);  loadB(0, 0);  CP_COMMIT();
    loadA(1, 64); loadB(1, 64); CP_COMMIT();
    CP_WAIT1(); __syncthreads();
    mma_chunk(0);
    __syncthreads();
    loadA(0, 128); loadB(0, 128); CP_COMMIT();
    CP_WAIT1(); __syncthreads();
    mma_chunk(1);
    __syncthreads();
    loadA(1, 192); loadB(1, 192); CP_COMMIT();
    CP_WAIT1(); __syncthreads();
    mma_chunk(0);
    CP_WAIT0(); __syncthreads();
    mma_chunk(1);
    __syncthreads();

    #pragma unroll
    for (int i = 0; i < 4; i++)
        #pragma unroll
        for (int j = 0; j < 4; j++)
            wmma::store_matrix_sync(&stage[wm * 64 + i * 16][wn * 64 + j * 16],
                                    acc[i][j], 132, wmma::mem_row_major);
    __syncthreads();

    {   // column softmax per 32-row head block (4 blocks); bias folded here
        int col = tid;
        #pragma unroll
        for (int hb = 0; hb < 4; hb++) {
            float vbuf[32];
            float m = -1e30f;
            #pragma unroll
            for (int rr = 0; rr < 32; rr++) {
                float vv = stage[hb * 32 + rr][col] + biasT[hb * 32 + rr];
                vbuf[rr] = vv; m = fmaxf(m, vv);
            }
            float s = 0.f;
            #pragma unroll
            for (int rr = 0; rr < 32; rr++) { vbuf[rr] = __expf(vbuf[rr] - m); s += vbuf[rr]; }
            float inv = SCALE / s;
            #pragma unroll
            for (int rr = 0; rr < 32; rr++)
                stage[hb * 32 + rr][col] = vbuf[rr] * inv;
        }
    }
    __syncthreads();
    #pragma unroll
    for (int it = 0; it < 16; it++) {
        int idx = tid + it * 128;
        int r = idx >> 4, c8 = (idx & 15) * 8;
        union { uint4 u; __nv_bfloat162 h2[4]; } o;
        #pragma unroll
        for (int u2 = 0; u2 < 4; u2++)
            o.h2[u2] = __floats2bfloat162_rn(stage[r][c8 + 2 * u2], stage[r][c8 + 2 * u2 + 1]);
        *(uint4*)(g_qt + (size_t)(b * Dm + et * 128 + r) * CT + (size_t)tt * 128 + c8) = o.u;
    }
}

// ---------------- K3b: kv GEMM, A resident, 2 t-tiles/block, fused exp/ctx ----------------
#define KV_B     67584
#define KV_KB    67584
#define KV_VB    84992
#define KV_BIAS  102400
#define KV_SS    102912
#define KV_SCR   103424
#define KV_HST   103424
#define KV_SMEM  112640

__global__ __launch_bounds__(128) void kv_fused() {
    extern __shared__ __align__(16) char sm[];
    bf (*A_res)[264] = (bf(*)[264])sm;
    bf (*B_s)[64][136] = (bf(*)[64][136])(sm + KV_B);
    bf (*kbuf)[136] = (bf(*)[136])(sm + KV_KB);
    bf (*vbuf)[136] = (bf(*)[136])(sm + KV_VB);
    float* biasT = (float*)(sm + KV_BIAS);
    float* S_s   = (float*)(sm + KV_SS);

    const int hp = blockIdx.x;   // head pair 0..3
    const int tg = blockIdx.y;   // 256 t-groups (2 tiles each)
    const int b  = blockIdx.z;

    const int tid = threadIdx.x;
    const int w = tid >> 5, lane = tid & 31;
    const int wm = w >> 1, wn = w & 1;

    auto rowmap = [&](int r) {
        return r < 64 ? (256 + hp * 64 + r) : (512 + hp * 64 + r - 64);
    };
    biasT[tid] = g_bias[b * E3 + rowmap(tid)];

    const bf* Wb = g_weff + (size_t)b * E3 * Dm;

    #pragma unroll
    for (int it = 0; it < 32; it++) {
        int idx = tid + it * 128;
        int r = idx >> 5, c8 = (idx & 31) * 8;
        cp16(&A_res[r][c8], Wb + (size_t)rowmap(r) * Dm + c8);
    }
    CP_COMMIT();

    for (int ti = 0; ti < 2; ti++) {
        const int tt = tg * 2 + ti;
        const bf* Bptr = g_xbf + (size_t)b * Dm * CT + (size_t)tt * 128;

        wmma::fragment<wmma::accumulator, 16, 16, 16, float> acc[4][4];
        #pragma unroll
        for (int i = 0; i < 4; i++)
            #pragma unroll
            for (int j = 0; j < 4; j++) wmma::fill_fragment(acc[i][j], 0.0f);

        auto loadB = [&](int s, int k0) {
            #pragma unroll
            for (int it = 0; it < 8; it++) {
                int idx = tid + it * 128;
                int r = idx >> 4, c8 = (idx & 15) * 8;
                cp16(&B_s[s][r][c8], Bptr + (size_t)(k0 + r) * CT + c8);
            }
        };
        auto mma_chunk = [&](int st, int k0) {
            #pragma unroll
            for (int kk = 0; kk < 64; kk += 16) {
                wmma::fragment<wmma::matrix_a, 16, 16, 16, bf, wmma::row_major> af[4];
                wmma::fragment<wmma::matrix_b, 16, 16, 16, bf, wmma::row_major> bfr[4];
                #pragma unroll
                for (int i = 0; i < 4; i++)
                    wmma::load_matrix_sync(af[i], &A_res[wm * 64 + i * 16][k0 + kk], 264);
                #pragma unroll
                for (int j = 0; j < 4; j++)
                    wmma::load_matrix_sync(bfr[j], &B_s[st][kk][wn * 64 + j * 16], 136);
                #pragma unroll
                for (int i = 0; i < 4; i++)
                    #pragma unroll
                    for (int j = 0; j < 4; j++)
                        wmma::mma_sync(acc[i][j], af[i], bfr[j], acc[i][j]);
            }
        };

        loadB(0, 0);  CP_COMMIT();
        loadB(1, 64); CP_COMMIT();
        CP_WAIT1(); __syncthreads();
        mma_chunk(0, 0);
        __syncthreads();
        loadB(0, 128); CP_COMMIT();
        CP_WAIT1(); __syncthreads();
        mma_chunk(1, 64);
        __syncthreads();
        loadB(1, 192); CP_COMMIT();
        CP_WAIT1(); __syncthreads();
        mma_chunk(0, 128);
        CP_WAIT0(); __syncthreads();
        mma_chunk(1, 192);
        __syncthreads();

        {
            float* scr = (float*)(sm + KV_SCR) + w * 320;   // [16][20] f32
            const int r2 = lane >> 1, cb = (lane & 1) * 8;
            #pragma unroll
            for (int i = 0; i < 4; i++) {
                int row = i * 16 + r2;
                float bsv = biasT[wm * 64 + row];
                float rowsum = 0.f;
                #pragma unroll
                for (int j = 0; j < 4; j++) {
                    wmma::store_matrix_sync(scr, acc[i][j], 20, wmma::mem_row_major);
                    __syncwarp();
                    union { uint4 u; __nv_bfloat162 h2[4]; } o;
                    if (wm == 0) {
                        #pragma unroll
                        for (int u = 0; u < 4; u++) {
                            float e0 = __expf(scr[r2 * 20 + cb + 2 * u] + bsv);
                            float e1 = __expf(scr[r2 * 20 + cb + 2 * u + 1] + bsv);
                            rowsum += e0 + e1;
                            o.h2[u] = __floats2bfloat162_rn(e0, e1);
                        }
                        *(uint4*)&kbuf[row][wn * 64 + j * 16 + cb] = o.u;
                    } else {
                        #pragma unroll
                        for (int u = 0; u < 4; u++) {
                            float e0 = (scr[r2 * 20 + cb + 2 * u] + bsv) * (1.0f / 1024.0f);
                            float e1 = (scr[r2 * 20 + cb + 2 * u + 1] + bsv) * (1.0f / 1024.0f);
                            o.h2[u] = __floats2bfloat162_rn(e0, e1);
                        }
                        *(uint4*)&vbuf[row][wn * 64 + j * 16 + cb] = o.u;
                    }
                    __syncwarp();
                }
                if (wm == 0) {
                    rowsum += __shfl_xor_sync(~0u, rowsum, 1);
                    if ((lane & 1) == 0) S_s[wn * 64 + row] = rowsum;
                }
            }
        }
        __syncthreads();

        const int c = tt >> 3, slot = tt & 7;
        const int bc = b * Cc + c;

        {
            int hl = w >> 1, th = w & 1;
            wmma::fragment<wmma::accumulator, 16, 16, 16, float> ca[2][2];
            #pragma unroll
            for (int i = 0; i < 2; i++)
                #pragma unroll
                for (int j = 0; j < 2; j++) wmma::fill_fragment(ca[i][j], 0.f);
            #pragma unroll
            for (int kk = 0; kk < 64; kk += 16) {
                wmma::fragment<wmma::matrix_a, 16, 16, 16, bf, wmma::row_major> af;
                wmma::fragment<wmma::matrix_b, 16, 16, 16, bf, wmma::col_major> bv;
                #pragma unroll
                for (int i = 0; i < 2; i++) {
                    wmma::load_matrix_sync(af, &kbuf[hl * 32 + i * 16][th * 64 + kk], 136);
                    #pragma unroll
                    for (int j = 0; j < 2; j++) {
                        wmma::load_matrix_sync(bv, &vbuf[hl * 32 + j * 16][th * 64 + kk], 136);
                        wmma::mma_sync(ca[i][j], af, bv, ca[i][j]);
                    }
                }
            }
            __syncthreads();
            float* hst = (float*)(sm + KV_HST) + hl * 1152;   // [32][36]
            if (th == 1) {
                #pragma unroll
                for (int i = 0; i < 2; i++)
                    #pragma unroll
                    for (int j = 0; j < 2; j++)
                        wmma::store_matrix_sync(&hst[(i * 16) * 36 + j * 16],
                                                ca[i][j], 36, wmma::mem_row_major);
            }
            __syncthreads();
            if (th == 0) {
                float* dst = g_ctxp + (((size_t)bc * 8 + slot) * Hh + hp * 2 + hl) * 1024;
                wmma::fragment<wmma::accumulator, 16, 16, 16, float> tmp;
                #pragma unroll
                for (int i = 0; i < 2; i++)
                    #pragma unroll
                    for (int j = 0; j < 2; j++) {
                        wmma::load_matrix_sync(tmp, &hst[(i * 16) * 36 + j * 16],
                                               36, wmma::mem_row_major);
                        for (int e = 0; e < tmp.num_elements; e++) ca[i][j].x[e] += tmp.x[e];
                        wmma::store_matrix_sync(dst + (i * 16) * 32 + j * 16,
                                                ca[i][j], 32, wmma::mem_row_major);
                    }
            }
        }
        if (tid < 64)
            g_Sp[((size_t)bc * 8 + slot) * 256 + hp * 64 + tid] = S_s[tid] + S_s[64 + tid];
        __syncthreads();
    }
}

// ---------------- K4: Mcat = W_out x blockdiag(ctx^T/S), reducing 8 slots ----------------
__global__ __launch_bounds__(256) void mcat_kernel() {
    int bc = blockIdx.x;
    __shared__ float Ssum[256];
    __shared__ bf ctxs[8192];
    int tid = threadIdx.x;
    {
        float s = 0.f;
        #pragma unroll
        for (int sl = 0; sl < 8; sl++)
            s += g_Sp[((size_t)bc * 8 + sl) * 256 + tid];
        Ssum[tid] = s;
    }
    __syncthreads();
    for (int i = tid; i < 8192; i += 256) {
        int h = i >> 10, fk = (i >> 5) & 31, fv = i & 31;
        float v = 0.f;
        #pragma unroll
        for (int sl = 0; sl < 8; sl++)
            v += g_ctxp[(((size_t)bc * 8 + sl) * Hh + h) * 1024 + fk * 32 + fv];
        ctxs[h * 1024 + fv * 32 + fk] = __float2bfloat16(v / Ssum[h * 32 + fk]);
    }
    __syncthreads();
    int e = tid;
    const bf* wrow = g_wout + e * Dm;
    #pragma unroll 1
    for (int h = 0; h < 8; h++) {
        float wv[32];
        #pragma unroll
        for (int fv = 0; fv < 32; fv++) wv[fv] = __bfloat162float(wrow[h * 32 + fv]);
        float o[32];
        #pragma unroll
        for (int fk = 0; fk < 32; fk++) o[fk] = 0.f;
        #pragma unroll
        for (int fv = 0; fv < 32; fv++) {
            float wf = wv[fv];
            const bf* cr = ctxs + h * 1024 + fv * 32;
            #pragma unroll
            for (int fk = 0; fk < 32; fk++) o[fk] += wf * __bfloat162float(cr[fk]);
        }
        __align__(16) bf ob[32];
        #pragma unroll
        for (int fk = 0; fk < 32; fk++) ob[fk] = __float2bfloat16(o[fk]);
        uint4* dst = (uint4*)(g_mcat + ((size_t)bc * Dm + e) * Dm + h * 32);
        const uint4* src = (const uint4*)ob;
        #pragma unroll
        for (int q2 = 0; q2 < 4; q2++) dst[q2] = src[q2];
    }
}

// ---------------- K5: out = Mcat[bc] @ q~ + out_b + x (2-stage, 3 CTAs/SM) ----------------
#define FG_SB    36864
#define FG_SBIAS 71680
#define FG_SMEM  72192

__global__ __launch_bounds__(128) void final_gemm(const float* __restrict__ x,
                                                  const float* __restrict__ out_b,
                                                  float* __restrict__ out) {
    extern __shared__ __align__(16) char sm[];
    bf (*A_s)[128][72] = (bf(*)[128][72])sm;
    bf (*B_s)[64][136] = (bf(*)[64][136])(sm + FG_SB);
    float (*stage)[132] = (float(*)[132])sm;
    float* biasO = (float*)(sm + FG_SBIAS);

    const int bx = blockIdx.x;   // t tile (8)
    const int by = blockIdx.y;   // e half (2)
    const int bc = blockIdx.z;   // 128
    const int b = bc >> 6, c = bc & 63;

    const int tid = threadIdx.x;
    const int w = tid >> 5;
    const int wm = w >> 1, wn = w & 1;

    biasO[tid] = out_b[by * 128 + tid];

    const bf* Aptr = g_mcat + (size_t)bc * Dm * Dm + (size_t)by * 128 * Dm;
    const bf* Bptr = g_qt + (size_t)b * Dm * CT + (size_t)c * Tt + (size_t)bx * 128;

    wmma::fragment<wmma::accumulator, 16, 16, 16, float> acc[4][4];
    #pragma unroll
    for (int i = 0; i < 4; i++)
        #pragma unroll
        for (int j = 0; j < 4; j++) wmma::fill_fragment(acc[i][j], 0.0f);

    auto loadA = [&](int s, int k0) {
        #pragma unroll
        for (int it = 0; it < 8; it++) {
            int idx = tid + it * 128;
            int r = idx >> 3, c8 = (idx & 7) * 8;
            cp16(&A_s[s][r][c8], Aptr + (size_t)r * Dm + k0 + c8);
        }
    };
    auto loadB = [&](int s, int k0) {
        #pragma unroll
        for (int it = 0; it < 8; it++) {
            int idx = tid + it * 128;
            int r = idx >> 4, c8 = (idx & 15) * 8;
            cp16(&B_s[s][r][c8], Bptr + (size_t)(k0 + r) * CT + c8);
        }
    };
    auto mma_chunk = [&](int st) {
        #pragma unroll
        for (int kk = 0; kk < 64; kk += 16) {
            wmma::fragment<wmma::matrix_a, 16, 16, 16, bf, wmma::row_major> af[4];
            wmma::fragment<wmma::matrix_b, 16, 16, 16, bf, wmma::row_major> bfr[4];
            #pragma unroll
            for (int i = 0; i < 4; i++)
                wmma::load_matrix_sync(af[i], &A_s[st][wm * 64 + i * 16][kk], 72);
            #pragma unroll
            for (int j = 0; j < 4; j++)
                wmma::load_matrix_sync(bfr[j], &B_s[st][kk][wn * 64 + j * 16], 136);
            #pragma unroll
            for (int i = 0; i < 4; i++)
                #pragma unroll
                for (int j = 0; j < 4; j++)
                    wmma::mma_sync(acc[i][j], af[i], bfr[j], acc[i][j]);
        }
    };

    loadA(0, 0);  loadB(0, 0);  CP_COMMIT();
    loadA(1, 64); loadB(1, 64); CP_COMMIT();
    CP_WAIT1(); __syncthreads();
    mma_chunk(0);
    __syncthreads();
    loadA(0, 128); loadB(0, 128); CP_COMMIT();
    CP_WAIT1(); __syncthreads();
    mma_chunk(1);
    __syncthreads();
    loadA(1, 192); loadB(1, 192); CP_COMMIT();
    CP_WAIT1(); __syncthreads();
    mma_chunk(0);
    CP_WAIT0(); __syncthreads();
    mma_chunk(1);
    __syncthreads();

    #pragma unroll
    for (int i = 0; i < 4; i++)
        #pragma unroll
        for (int j = 0; j < 4; j++)
            wmma::store_matrix_sync(&stage[wm * 64 + i * 16][wn * 64 + j * 16],
                                    acc[i][j], 132, wmma::mem_row_major);
    __syncthreads();

    #pragma unroll
    for (int it = 0; it < 32; it++) {
        int idx = tid + it * 128;
        int r = idx >> 5, c4 = (idx & 31) * 4;
        int e = by * 128 + r;
        size_t gi = ((size_t)(b * Dm + e) * Cc + c) * Tt + (size_t)bx * 128 + c4;
        float4 xv = *(const float4*)(x + gi);
        float bo = biasO[r];
        float4 o;
        o.x = stage[r][c4 + 0] + bo + xv.x;
        o.y = stage[r][c4 + 1] + bo + xv.y;
        o.z = stage[r][c4 + 2] + bo + xv.z;
        o.w = stage[r][c4 + 3] + bo + xv.w;
        *(float4*)(out + gi) = o;
    }
}

// ---------------- launch ----------------
extern "C" void kernel_launch(void* const* d_in, const int* in_sizes, int n_in,
                              void* d_out, int out_size) {
    const float* x     = (const float*)d_in[0];
    const float* in_w  = (const float*)d_in[1];
    const float* in_b  = (const float*)d_in[2];
    const float* out_w = (const float*)d_in[3];
    const float* out_b = (const float*)d_in[4];
    float* out = (float*)d_out;

    cudaFuncSetAttribute(q_gemm, cudaFuncAttributeMaxDynamicSharedMemorySize, QG_SMEM);
    cudaFuncSetAttribute(kv_fused, cudaFuncAttributeMaxDynamicSharedMemorySize, KV_SMEM);
    cudaFuncSetAttribute(final_gemm, cudaFuncAttributeMaxDynamicSharedMemorySize, FG_SMEM);

    stats_cvt<<<Bn * Dm, 256>>>(x);
    prep_weights<<<Bn * E3, 256>>>(in_w, in_b);
    conv_outw<<<Dm * Dm / 256, 256>>>(out_w);
    q_gemm<<<dim3(2, CT / 128, Bn), 128, QG_SMEM>>>();
    kv_fused<<<dim3(4, CT / 256, Bn), 128, KV_SMEM>>>();
    mcat_kernel<<<Bn * Cc, 256>>>();
    final_gemm<<<dim3(Tt / 128, 2, Bn * Cc), 128, FG_SMEM>>>(x, out_b, out);
}